// round 1
// baseline (speedup 1.0000x reference)
#include <cuda_runtime.h>
#include <cstddef>

// Fixed problem shape (from reference setup_inputs):
//   bs=32, P=256 -> V=65536, F=2*(P-1)^2=130050, C=6
#define BS 32
#define NV 65536
#define NF 130050
#define NC 6

// Scratch: per-batch face normals, padded to float4 for aligned gathers.
// 32 * 130050 * 16 B = 66.6 MB (device global, allocation-free).
__device__ float4 g_fn[(size_t)BS * NF];

__global__ void __launch_bounds__(256)
face_normals_kernel(const float* __restrict__ points,
                    const int*   __restrict__ faces)
{
    int i = blockIdx.x * blockDim.x + threadIdx.x;
    if (i >= BS * NF) return;
    int b = i / NF;
    int f = i - b * NF;

    int i0 = faces[3 * f + 0];
    int i1 = faces[3 * f + 1];
    int i2 = faces[3 * f + 2];

    const float* __restrict__ px = points + (size_t)b * 3 * NV;
    const float* __restrict__ py = px + NV;
    const float* __restrict__ pz = py + NV;

    float x0 = px[i0], y0 = py[i0], z0 = pz[i0];
    float ax = px[i1] - x0, ay = py[i1] - y0, az = pz[i1] - z0;
    float bx = px[i2] - x0, by = py[i2] - y0, bz = pz[i2] - z0;

    // cross(v1, v2)
    float cx = ay * bz - az * by;
    float cy = az * bx - ax * bz;
    float cz = ax * by - ay * bx;

    float n   = sqrtf(cx * cx + cy * cy + cz * cz);
    float inv = 1.0f / fmaxf(n, 1e-12f);

    g_fn[i] = make_float4(cx * inv, cy * inv, cz * inv, 0.0f);
}

__global__ void __launch_bounds__(256)
vertex_normals_kernel(const int*   __restrict__ vti,   // (V, C)
                      const float* __restrict__ vtw,   // (V, C)
                      float*       __restrict__ out)   // (BS, V, 3)
{
    int i = blockIdx.x * blockDim.x + threadIdx.x;
    if (i >= BS * NV) return;
    int b = i / NV;
    int v = i - b * NV;

    const float4* __restrict__ fnb = g_fn + (size_t)b * NF;

    float ax = 0.0f, ay = 0.0f, az = 0.0f;
#pragma unroll
    for (int c = 0; c < NC; c++) {
        int   f = vti[v * NC + c];
        float w = vtw[v * NC + c];
        float4 n = __ldg(fnb + f);
        ax += n.x * w;
        ay += n.y * w;
        az += n.z * w;
    }

    float n   = sqrtf(ax * ax + ay * ay + az * az);
    float inv = 1.0f / fmaxf(n, 1e-12f);

    size_t o = (size_t)i * 3;
    out[o + 0] = ax * inv;
    out[o + 1] = ay * inv;
    out[o + 2] = az * inv;
}

extern "C" void kernel_launch(void* const* d_in, const int* in_sizes, int n_in,
                              void* d_out, int out_size)
{
    const float* points = (const float*)d_in[0];  // (BS, 3, V)
    const int*   faces  = (const int*)  d_in[1];  // (F, 3)
    const int*   vti    = (const int*)  d_in[2];  // (V, C)
    const float* vtw    = (const float*)d_in[3];  // (V, C, 1)
    float*       out    = (float*)d_out;          // (BS, V, 3)

    {
        int total = BS * NF;
        int threads = 256;
        int blocks = (total + threads - 1) / threads;
        face_normals_kernel<<<blocks, threads>>>(points, faces);
    }
    {
        int total = BS * NV;
        int threads = 256;
        int blocks = (total + threads - 1) / threads;
        vertex_normals_kernel<<<blocks, threads>>>(vti, vtw, out);
    }
}

// round 2
// speedup vs baseline: 2.9238x; 2.9238x over previous
#include <cuda_runtime.h>
#include <cstddef>

// Fixed problem shape: bs=32, V=65536, F=130050, C=6.  BS == warp size.
#define BS 32
#define NV 65536
#define NF 130050
#define NC 6

// Scratch (device globals; allocation-free):
//   ptsT[v][b] : batch-innermost padded points, 65536*32*16B = 32 MB
//   fn  [f][b] : batch-innermost face normals, 130050*32*16B = 66.6 MB
__device__ float4 g_ptsT[(size_t)NV * BS];
__device__ float4 g_fn[(size_t)NF * BS];

// ---------------------------------------------------------------------------
// Kernel 1: transpose points (BS,3,V) -> ptsT[(v)*32 + b] = {x,y,z,0}
// ---------------------------------------------------------------------------
__global__ void __launch_bounds__(256)
transpose_kernel(const float* __restrict__ points)
{
    __shared__ float s[3][32][33];          // [coord][b][v_in_tile]
    int v0 = blockIdx.x * 32;
    int tx = threadIdx.x;                   // phase1: v offset; phase2: b

    // Phase 1: coalesced reads along v for each (b, c)
    for (int b = threadIdx.y; b < 32; b += 8) {
#pragma unroll
        for (int c = 0; c < 3; c++)
            s[c][b][tx] = points[((size_t)b * 3 + c) * NV + v0 + tx];
    }
    __syncthreads();

    // Phase 2: coalesced float4 writes along b for each v
    for (int vy = threadIdx.y; vy < 32; vy += 8) {
        g_ptsT[(size_t)(v0 + vy) * BS + tx] =
            make_float4(s[0][tx][vy], s[1][tx][vy], s[2][tx][vy], 0.0f);
    }
}

// ---------------------------------------------------------------------------
// Kernel 2: face normals.  warp = face, lane = batch.
// All index loads are warp-uniform; all point loads / normal stores coalesced.
// ---------------------------------------------------------------------------
__global__ void __launch_bounds__(256)
face_normals_kernel(const int* __restrict__ faces)
{
    int warp = (blockIdx.x * blockDim.x + threadIdx.x) >> 5;
    int lane = threadIdx.x & 31;            // = batch index
    if (warp >= NF) return;
    int f = warp;

    int i0 = faces[3 * f + 0];
    int i1 = faces[3 * f + 1];
    int i2 = faces[3 * f + 2];

    float4 p0 = g_ptsT[(size_t)i0 * BS + lane];
    float4 p1 = g_ptsT[(size_t)i1 * BS + lane];
    float4 p2 = g_ptsT[(size_t)i2 * BS + lane];

    float ax = p1.x - p0.x, ay = p1.y - p0.y, az = p1.z - p0.z;
    float bx = p2.x - p0.x, by = p2.y - p0.y, bz = p2.z - p0.z;

    float cx = ay * bz - az * by;
    float cy = az * bx - ax * bz;
    float cz = ax * by - ay * bx;

    float n   = sqrtf(cx * cx + cy * cy + cz * cz);
    float inv = 1.0f / fmaxf(n, 1e-12f);

    g_fn[(size_t)f * BS + lane] = make_float4(cx * inv, cy * inv, cz * inv, 0.0f);
}

// ---------------------------------------------------------------------------
// Kernel 3: vertex normals.  warp = vertex, lane = batch.
// 6 coalesced float4 gathers; output restaged via smem for coalesced writes.
// ---------------------------------------------------------------------------
__global__ void __launch_bounds__(256)
vertex_normals_kernel(const int*   __restrict__ vti,   // (V, C)
                      const float* __restrict__ vtw,   // (V, C)
                      float*       __restrict__ out)   // (BS, V, 3)
{
    __shared__ float so[8][32][3];          // [v_in_block][b][xyz]

    int wid  = threadIdx.x >> 5;            // 0..7
    int lane = threadIdx.x & 31;            // = batch
    int v0   = blockIdx.x * 8;
    int v    = v0 + wid;

    float ax = 0.0f, ay = 0.0f, az = 0.0f;
#pragma unroll
    for (int c = 0; c < NC; c++) {
        int   f = vti[v * NC + c];          // warp-uniform
        float w = vtw[v * NC + c];          // warp-uniform
        float4 n = g_fn[(size_t)f * BS + lane];
        ax = fmaf(n.x, w, ax);
        ay = fmaf(n.y, w, ay);
        az = fmaf(n.z, w, az);
    }

    float n   = sqrtf(ax * ax + ay * ay + az * az);
    float inv = 1.0f / fmaxf(n, 1e-12f);

    so[wid][lane][0] = ax * inv;
    so[wid][lane][1] = ay * inv;
    so[wid][lane][2] = az * inv;
    __syncthreads();

    // Write out (b, v, 3): thread t -> b = t>>3, j = t&7 writes 12 contiguous B
    int b = threadIdx.x >> 3;
    int j = threadIdx.x & 7;
    size_t o = ((size_t)b * NV + (v0 + j)) * 3;
    out[o + 0] = so[j][b][0];
    out[o + 1] = so[j][b][1];
    out[o + 2] = so[j][b][2];
}

// ---------------------------------------------------------------------------
extern "C" void kernel_launch(void* const* d_in, const int* in_sizes, int n_in,
                              void* d_out, int out_size)
{
    const float* points = (const float*)d_in[0];  // (BS, 3, V)
    const int*   faces  = (const int*)  d_in[1];  // (F, 3)
    const int*   vti    = (const int*)  d_in[2];  // (V, C)
    const float* vtw    = (const float*)d_in[3];  // (V, C, 1)
    float*       out    = (float*)d_out;          // (BS, V, 3)

    // K1: 2048 blocks of (32,8)
    {
        dim3 blk(32, 8);
        transpose_kernel<<<NV / 32, blk>>>(points);
    }
    // K2: one warp per face
    {
        int warps_per_block = 8;
        int blocks = (NF + warps_per_block - 1) / warps_per_block;
        face_normals_kernel<<<blocks, 256>>>(faces);
    }
    // K3: one warp per vertex (8 per block)
    {
        int blocks = NV / 8;
        vertex_normals_kernel<<<blocks, 256>>>(vti, vtw, out);
    }
}

// round 3
// speedup vs baseline: 3.2490x; 1.1112x over previous
#include <cuda_runtime.h>
#include <cstddef>

// Fixed problem shape: bs=32, V=65536, F=130050, C=6.  BS == warp size.
#define BS 32
#define NV 65536
#define NF 130050
#define NC 6

// Scratch (device globals): SoA coordinate planes, batch-innermost.
//   g_ptsT[c][v*32 + b] : 3 * 65536*32*4B = 25.2 MB
//   g_fn  [c][f*32 + b] : 3 * 130050*32*4B = 50.0 MB
__device__ float g_ptsT[3][(size_t)NV * BS];
__device__ float g_fn[3][(size_t)NF * BS];

// ---------------------------------------------------------------------------
// Kernel 1: transpose points (BS,3,V) -> SoA planes [c][v*32+b].
// 64-vertex tile per block; float4 global loads; conflict-light smem restage.
// ---------------------------------------------------------------------------
#define TV 64
__global__ void __launch_bounds__(256)
transpose_kernel(const float* __restrict__ points)
{
    __shared__ float s2[3 * TV][33];        // [c*TV + j][b]
    int v0 = blockIdx.x * TV;
    int t  = threadIdx.x;

    // Phase 1: 96 rows (b*3+c) x 16 float4 columns = 1536 loads, 6 per thread.
#pragma unroll
    for (int k = 0; k < 6; k++) {
        int idx  = t + k * 256;             // 0..1535
        int row  = idx >> 4;                // 0..95 = b*3 + c
        int col4 = idx & 15;
        int b    = row / 3;
        int c    = row - 3 * b;
        float4 p = *(const float4*)&points[(size_t)row * NV + v0 + col4 * 4];
        int jb = c * TV + col4 * 4;
        s2[jb + 0][b] = p.x;
        s2[jb + 1][b] = p.y;
        s2[jb + 2][b] = p.z;
        s2[jb + 3][b] = p.w;
    }
    __syncthreads();

    // Phase 2: each warp streams rows; 128B coalesced stores per row.
    int lane = t & 31;
    int wid  = t >> 5;
#pragma unroll
    for (int r = wid; r < 3 * TV; r += 8) {
        int c = r >> 6;                     // r / TV
        int j = r & 63;                     // r % TV
        g_ptsT[c][(size_t)(v0 + j) * BS + lane] = s2[r][lane];
    }
}

// ---------------------------------------------------------------------------
// Kernel 2: face normals.  warp = face, lane = batch.
// 9 coalesced 128B loads, 3 coalesced 128B stores; indices warp-uniform.
// ---------------------------------------------------------------------------
__global__ void __launch_bounds__(256)
face_normals_kernel(const int* __restrict__ faces)
{
    int w    = (blockIdx.x * 256 + threadIdx.x) >> 5;
    int lane = threadIdx.x & 31;            // = batch
    if (w >= NF) return;

    int i0 = __ldg(&faces[3 * w + 0]);
    int i1 = __ldg(&faces[3 * w + 1]);
    int i2 = __ldg(&faces[3 * w + 2]);

    size_t o0 = (size_t)i0 * BS + lane;
    size_t o1 = (size_t)i1 * BS + lane;
    size_t o2 = (size_t)i2 * BS + lane;

    float x0 = g_ptsT[0][o0], y0 = g_ptsT[1][o0], z0 = g_ptsT[2][o0];
    float ax = g_ptsT[0][o1] - x0, ay = g_ptsT[1][o1] - y0, az = g_ptsT[2][o1] - z0;
    float bx = g_ptsT[0][o2] - x0, by = g_ptsT[1][o2] - y0, bz = g_ptsT[2][o2] - z0;

    float cx = ay * bz - az * by;
    float cy = az * bx - ax * bz;
    float cz = ax * by - ay * bx;

    float ss  = cx * cx + cy * cy + cz * cz;
    float n   = sqrtf(ss);
    float inv = 1.0f / fmaxf(n, 1e-12f);

    size_t of = (size_t)w * BS + lane;
    g_fn[0][of] = cx * inv;
    g_fn[1][of] = cy * inv;
    g_fn[2][of] = cz * inv;
}

// ---------------------------------------------------------------------------
// Kernel 3: vertex normals.  warp = vertex, lane = batch.
// 18 coalesced 128B gathers; smem restage for coalesced output writes.
// ---------------------------------------------------------------------------
__global__ void __launch_bounds__(256)
vertex_normals_kernel(const int*   __restrict__ vti,   // (V, C)
                      const float* __restrict__ vtw,   // (V, C)
                      float*       __restrict__ out)   // (BS, V, 3)
{
    __shared__ float so[8][33][3];          // [v_in_block][b][xyz] (pad row 33)

    int wid  = threadIdx.x >> 5;            // 0..7
    int lane = threadIdx.x & 31;            // = batch
    int v0   = blockIdx.x * 8;
    int v    = v0 + wid;

    int   f[NC];
    float wgt[NC];
#pragma unroll
    for (int c = 0; c < NC; c++) {
        f[c]   = __ldg(&vti[v * NC + c]);   // warp-uniform
        wgt[c] = __ldg(&vtw[v * NC + c]);   // warp-uniform
    }

    float ax = 0.0f, ay = 0.0f, az = 0.0f;
#pragma unroll
    for (int c = 0; c < NC; c++) {
        size_t o = (size_t)f[c] * BS + lane;
        ax = fmaf(g_fn[0][o], wgt[c], ax);
        ay = fmaf(g_fn[1][o], wgt[c], ay);
        az = fmaf(g_fn[2][o], wgt[c], az);
    }

    float ss  = ax * ax + ay * ay + az * az;
    float n   = sqrtf(ss);
    float inv = 1.0f / fmaxf(n, 1e-12f);

    so[wid][lane][0] = ax * inv;
    so[wid][lane][1] = ay * inv;
    so[wid][lane][2] = az * inv;
    __syncthreads();

    // Write out (b, v, 3): thread t -> b = t>>3, j = t&7 writes 12 contiguous B
    int b = threadIdx.x >> 3;
    int j = threadIdx.x & 7;
    size_t o = ((size_t)b * NV + (v0 + j)) * 3;
    out[o + 0] = so[j][b][0];
    out[o + 1] = so[j][b][1];
    out[o + 2] = so[j][b][2];
}

// ---------------------------------------------------------------------------
extern "C" void kernel_launch(void* const* d_in, const int* in_sizes, int n_in,
                              void* d_out, int out_size)
{
    const float* points = (const float*)d_in[0];  // (BS, 3, V)
    const int*   faces  = (const int*)  d_in[1];  // (F, 3)
    const int*   vti    = (const int*)  d_in[2];  // (V, C)
    const float* vtw    = (const float*)d_in[3];  // (V, C, 1)
    float*       out    = (float*)d_out;          // (BS, V, 3)

    transpose_kernel<<<NV / TV, 256>>>(points);

    {
        int warps_per_block = 8;
        int blocks = (NF + warps_per_block - 1) / warps_per_block;
        face_normals_kernel<<<blocks, 256>>>(faces);
    }

    vertex_normals_kernel<<<NV / 8, 256>>>(vti, vtw, out);
}